// round 14
// baseline (speedup 1.0000x reference)
#include <cuda_runtime.h>
#include <cuda_fp16.h>
#include <cstdint>

// GAT layer, N=8192, Fin=128, Fout=64.
// inputs: x [N,128] f32, adj [N,N] f32 (0/1), W [128,64] f32, a [128,1] f32
// output: [N,64] f32

#define N      8192
#define FOUT   64
#define TI     128
#define TJ     32
#define JSPLIT 16
#define JRANGE (N / JSPLIT)     // 512
#define NT     (JRANGE / TJ)    // 16

#define ADJ_STR 40                        // floats per adj smem row (160 B)
#define STAGE_ADJ_B (TI * ADJ_STR * 4)    // 20480
#define STAGE_WH_B  (TJ * 72 * 2)         // 4608 (144B rows)
#define STAGE_B     (STAGE_ADJ_B + STAGE_WH_B)   // 25088
#define SMEMB_BYTES (3 * STAGE_B)         // 75264 (mbarriers live in row-0 pad)

// ---------------- device scratch ----------------
__device__ float2 g_E1P[N];
__device__ __half g_E2XH[N];
__device__ __half g_E2YH[N];
__device__ __half g_Wh_h[N * FOUT];          // Wh [j][f] fp16
__device__ float  g_acc[JSPLIT][N * FOUT];
__device__ float  g_den[JSPLIT][N];

// ---------------- helpers ----------------
#define CP_ASYNC16(dst, src) \
    asm volatile("cp.async.cg.shared.global [%0], [%1], 16;" :: "r"(dst), "l"(src))
#define CP_COMMIT() asm volatile("cp.async.commit_group;")
#define CP_WAIT2()  asm volatile("cp.async.wait_group 2;" ::: "memory")

#define MBAR_INIT(a, c) \
    asm volatile("mbarrier.init.shared.b64 [%0], %1;" :: "r"(a), "r"(c) : "memory")
#define MBAR_ARRIVE_TX(a, tx) \
    asm volatile("mbarrier.arrive.expect_tx.shared.b64 _, [%0], %1;" :: "r"(a), "r"(tx) : "memory")
#define BULK_G2S(dst, src, bytes, mbar)                                        \
    asm volatile("cp.async.bulk.shared::cluster.global.mbarrier::complete_tx::bytes " \
                 "[%0], [%1], %2, [%3];"                                       \
                 :: "r"(dst), "l"(src), "r"(bytes), "r"(mbar) : "memory")
#define MBAR_WAIT(a, par) do {                                                 \
    asm volatile("{\n\t.reg .pred P1;\n\t"                                     \
        "WAIT_LOOP_%=:\n\t"                                                    \
        "mbarrier.try_wait.parity.acquire.cta.shared::cta.b64 P1, [%0], %1, 0x989680;\n\t" \
        "@P1 bra.uni WAIT_DONE_%=;\n\t"                                        \
        "bra.uni WAIT_LOOP_%=;\n\t"                                            \
        "WAIT_DONE_%=:\n\t}"                                                   \
        :: "r"(a), "r"(par) : "memory");                                       \
} while (0)
#define FENCE_ASYNC() asm volatile("fence.proxy.async.shared::cta;" ::: "memory")

#define LDSM_X4(d0, d1, d2, d3, addr)                                          \
    asm volatile("ldmatrix.sync.aligned.m8n8.x4.shared.b16 "                   \
                 "{%0,%1,%2,%3}, [%4];"                                        \
                 : "=r"(d0), "=r"(d1), "=r"(d2), "=r"(d3) : "r"(addr))
#define LDSM_X4_T(d0, d1, d2, d3, addr)                                        \
    asm volatile("ldmatrix.sync.aligned.m8n8.x4.trans.shared.b16 "             \
                 "{%0,%1,%2,%3}, [%4];"                                        \
                 : "=r"(d0), "=r"(d1), "=r"(d2), "=r"(d3) : "r"(addr))

#define MMA_F16(D, A, B0, B1)                                                 \
    asm("mma.sync.aligned.m16n8k16.row.col.f32.f16.f16.f32 "                  \
        "{%0,%1,%2,%3},{%4,%5,%6,%7},{%8,%9},{%0,%1,%2,%3};"                  \
        : "+f"((D)[0]), "+f"((D)[1]), "+f"((D)[2]), "+f"((D)[3])              \
        : "r"((A)[0]), "r"((A)[1]), "r"((A)[2]), "r"((A)[3]),                 \
          "r"(B0), "r"(B1))
#define MMA_F16R(D, A0, A1, A2, A3, B0, B1)                                   \
    asm("mma.sync.aligned.m16n8k16.row.col.f32.f16.f16.f32 "                  \
        "{%0,%1,%2,%3},{%4,%5,%6,%7},{%8,%9},{%0,%1,%2,%3};"                  \
        : "+f"((D)[0]), "+f"((D)[1]), "+f"((D)[2]), "+f"((D)[3])              \
        : "r"(A0), "r"(A1), "r"(A2), "r"(A3), "r"(B0), "r"(B1))

// ============================================================
// Kernel A: Wh = x@W via fp16 MMA (proven 6.7us R13 version).
// ============================================================
#define P_XH 0
#define P_WH 17408
#define P_A  (17408 + 18432)
#define PREP_SMEM (P_A + 512)

__global__ void __launch_bounds__(128) gat_prep(const float* __restrict__ x,
                                                const float* __restrict__ W,
                                                const float* __restrict__ a)
{
    extern __shared__ char psm[];
    __half* xh = (__half*)(psm + P_XH);
    __half* wh = (__half*)(psm + P_WH);
    float*  aS = (float*)(psm + P_A);

    const int t = threadIdx.x;
    const int row0 = blockIdx.x * 64;

    const float* xb = x + (size_t)row0 * 128;
    #pragma unroll
    for (int q = 0; q < 16; q++) {
        const int flat = (q * 128 + t) * 4;
        const int r = flat >> 7, c = flat & 127;
        float4 v = *(const float4*)&xb[flat];
        __half2 h0 = __floats2half2_rn(v.x, v.y);
        __half2 h1 = __floats2half2_rn(v.z, v.w);
        uint2 u = make_uint2(*(uint32_t*)&h0, *(uint32_t*)&h1);
        *(uint2*)&xh[r * 136 + c] = u;
    }
    #pragma unroll
    for (int q = 0; q < 16; q++) {
        const int flat = (q * 128 + t) * 4;
        const int k = flat >> 6, f = flat & 63;
        float4 v = *(const float4*)&W[flat];
        __half2 h0 = __floats2half2_rn(v.x, v.y);
        __half2 h1 = __floats2half2_rn(v.z, v.w);
        uint2 u = make_uint2(*(uint32_t*)&h0, *(uint32_t*)&h1);
        *(uint2*)&wh[k * 72 + f] = u;
    }
    if (t < 32) *(float4*)&aS[t * 4] = *(const float4*)&a[t * 4];
    __syncthreads();

    const int lane = t & 31, warp = t >> 5;
    const int rbase = warp * 16;
    const int mm = lane >> 3;
    const uint32_t sb = (uint32_t)__cvta_generic_to_shared(psm);

    const uint32_t A_base = sb + P_XH +
        ((rbase + (mm & 1) * 8 + (lane & 7)) * 136 + (mm >> 1) * 8) * 2;
    const int ldsm_row = (mm & 1) * 8 + (lane & 7);
    const int ldsm_f   = mm >> 1;
    const uint32_t B_base = sb + P_WH + ldsm_row * 144 + ldsm_f * 16;

    float c[8][4];
    #pragma unroll
    for (int nt = 0; nt < 8; nt++)
        #pragma unroll
        for (int e = 0; e < 4; e++) c[nt][e] = 0.f;

    #pragma unroll
    for (int kc = 0; kc < 8; kc++) {
        uint32_t A0, A1, A2, A3;
        LDSM_X4(A0, A1, A2, A3, A_base + kc * 32);
        #pragma unroll
        for (int p = 0; p < 4; p++) {
            uint32_t q0, q1, q2, q3;
            LDSM_X4_T(q0, q1, q2, q3, B_base + kc * 16 * 144 + p * 32);
            MMA_F16R(c[2 * p],     A0, A1, A2, A3, q0, q1);
            MMA_F16R(c[2 * p + 1], A0, A1, A2, A3, q2, q3);
        }
    }

    const int qq = lane & 3, r0 = lane >> 2;
    const int rowlo = row0 + rbase + r0;
    float p1lo = 0.f, p1hi = 0.f, p2lo = 0.f, p2hi = 0.f;
    #pragma unroll
    for (int nt = 0; nt < 8; nt++) {
        const int col = nt * 8 + 2 * qq;
        const float a1l = aS[col], a1h = aS[col + 1];
        const float a2l = aS[64 + col], a2h = aS[64 + col + 1];
        p1lo += c[nt][0] * a1l + c[nt][1] * a1h;
        p1hi += c[nt][2] * a1l + c[nt][3] * a1h;
        p2lo += c[nt][0] * a2l + c[nt][1] * a2h;
        p2hi += c[nt][2] * a2l + c[nt][3] * a2h;
        __half2 h0 = __floats2half2_rn(c[nt][0], c[nt][1]);
        __half2 h1 = __floats2half2_rn(c[nt][2], c[nt][3]);
        *(uint32_t*)&g_Wh_h[(size_t)rowlo * 64 + col]       = *(uint32_t*)&h0;
        *(uint32_t*)&g_Wh_h[(size_t)(rowlo + 8) * 64 + col] = *(uint32_t*)&h1;
    }
    p1lo += __shfl_xor_sync(0xffffffffu, p1lo, 1);
    p1lo += __shfl_xor_sync(0xffffffffu, p1lo, 2);
    p1hi += __shfl_xor_sync(0xffffffffu, p1hi, 1);
    p1hi += __shfl_xor_sync(0xffffffffu, p1hi, 2);
    p2lo += __shfl_xor_sync(0xffffffffu, p2lo, 1);
    p2lo += __shfl_xor_sync(0xffffffffu, p2lo, 2);
    p2hi += __shfl_xor_sync(0xffffffffu, p2hi, 1);
    p2hi += __shfl_xor_sync(0xffffffffu, p2hi, 2);

    if (qq == 0) {
        g_E1P[rowlo]      = make_float2(__expf(p1lo), __expf(0.2f * p1lo));
        g_E1P[rowlo + 8]  = make_float2(__expf(p1hi), __expf(0.2f * p1hi));
        g_E2XH[rowlo]     = __float2half(__expf(p2lo));
        g_E2YH[rowlo]     = __float2half(__expf(0.2f * p2lo));
        g_E2XH[rowlo + 8] = __float2half(__expf(p2hi));
        g_E2YH[rowlo + 8] = __float2half(__expf(0.2f * p2hi));
    }
}

// ============================================================
// Kernel B: adj via cp.async.bulk (TMA pipe) + Wh cp.async ring + fp16 MMA.
// grid (64, 16) x 128 threads (4 warps), 3 blocks/SM. 32 MMAs/warp/tile.
// mbarriers in the unused row-0 pad bytes [128,152) of stage 0.
// ============================================================
__global__ void __launch_bounds__(128, 3) gat_attn(const float* __restrict__ adj)
{
    extern __shared__ char smem[];
    const int t = threadIdx.x, lane = t & 31, warp = t >> 5;
    const int ib = blockIdx.x, js = blockIdx.y;
    const int i_base = ib * TI, i_warp = i_base + warp * 32;
    const int j0 = js * JRANGE;
    const int r0 = lane >> 2, c0 = (lane & 3) * 2;

    const uint32_t sb = (uint32_t)__cvta_generic_to_shared(smem);
    const uint32_t mbar0 = sb + 128;      // 3 x 8B in stage-0 row-0 pad

    // adj bulk: thread t owns row t (128B per tile)
    const float* adj_src = adj + (size_t)(i_base + t) * N + j0;
    // Wh staging: 2 x 16B chunks per thread
    const int arow = t >> 3, aseg = t & 7;
    const __half* wh_base = g_Wh_h + (size_t)(j0 + arow) * 64 + aseg * 8;

#define PREFETCH(tt)                                                           \
    do {                                                                       \
        const int s_ = (tt) % 3;                                               \
        const uint32_t st_ = sb + s_ * STAGE_B;                                \
        MBAR_ARRIVE_TX(mbar0 + s_ * 8, 128u);                                  \
        BULK_G2S(st_ + t * (ADJ_STR * 4), adj_src + (tt) * TJ, 128u,           \
                 mbar0 + s_ * 8);                                              \
        const uint32_t wst_ = st_ + STAGE_ADJ_B;                               \
        const __half* ws_ = wh_base + (size_t)((tt) * TJ) * 64;                \
        CP_ASYNC16(wst_ + arow * 144 + aseg * 16, ws_);                        \
        CP_ASYNC16(wst_ + (16 + arow) * 144 + aseg * 16, ws_ + 16 * 64);       \
        CP_COMMIT();                                                           \
    } while (0)

    if (t == 0) {
        MBAR_INIT(mbar0,      128);
        MBAR_INIT(mbar0 + 8,  128);
        MBAR_INIT(mbar0 + 16, 128);
        FENCE_ASYNC();
    }
    __syncthreads();

    PREFETCH(0); PREFETCH(1); PREFETCH(2);

    // e1 fp16 splats (invariant)
    __half2 e1x2[2][2], e1y2[2][2];
    #pragma unroll
    for (int mt = 0; mt < 2; mt++)
        #pragma unroll
        for (int aa = 0; aa < 2; aa++) {
            float2 e1f = g_E1P[i_warp + mt * 16 + aa * 8 + r0];
            e1x2[mt][aa] = __half2half2(__float2half(e1f.x));
            e1y2[mt][aa] = __half2half2(__float2half(e1f.y));
        }

    float acc[2][8][4];
    #pragma unroll
    for (int mt = 0; mt < 2; mt++)
        #pragma unroll
        for (int nt = 0; nt < 8; nt++)
            #pragma unroll
            for (int e = 0; e < 4; e++) acc[mt][nt][e] = 0.f;
    float den4[2][2] = {{0.f, 0.f}, {0.f, 0.f}};

    // ldmatrix lane map (x4.trans)
    const int mm = lane >> 3;
    const int ldsm_row = (mm & 1) * 8 + (lane & 7);
    const int ldsm_f   = mm >> 1;

    #pragma unroll 1
    for (int it = 0; it < NT; it++) {
        const int s = it % 3;
        const int jt = j0 + it * TJ;
        const int phase = (it / 3) & 1;
        MBAR_WAIT(mbar0 + s * 8, phase);   // adj ready (acquire)
        CP_WAIT2();                         // own Wh groups landed
        __syncthreads();                    // everyone's Wh landed

        // ---- e2 fp16 pair loads (L1-hot) ----
        __half2 ex2[2][2], ey2[2][2];
        #pragma unroll
        for (int kt = 0; kt < 2; kt++)
            #pragma unroll
            for (int hh = 0; hh < 2; hh++) {
                const int jj = jt + kt * 16 + hh * 8 + c0;
                ex2[kt][hh] = *(const __half2*)&g_E2XH[jj];
                ey2[kt][hh] = *(const __half2*)&g_E2YH[jj];
            }

        // ---- A fragments (P) from smem adj ----
        const float* adjS = (const float*)(smem + s * STAGE_B);
        uint32_t afr[2][2][4];
        #pragma unroll
        for (int mt = 0; mt < 2; mt++)
            #pragma unroll
            for (int kt = 0; kt < 2; kt++)
                #pragma unroll
                for (int aa = 0; aa < 2; aa++)
                    #pragma unroll
                    for (int hh = 0; hh < 2; hh++) {
                        const int R = warp * 32 + mt * 16 + aa * 8 + r0;
                        float2 ad = *(const float2*)&adjS[R * ADJ_STR +
                                                          kt * 16 + hh * 8 + c0];
                        __half2 ah = __floats2half2_rn(ad.x, ad.y);
                        __half2 u  = __hmul2(e1x2[mt][aa], ex2[kt][hh]);
                        __half2 v  = __hmul2(e1y2[mt][aa], ey2[kt][hh]);
                        __half2 p  = __hmul2(__hmax2(u, v), ah);
                        afr[mt][kt][aa + 2 * hh] = *(uint32_t*)&p;
                    }

        // ---- den on ALU pipe (same rounded p values) ----
        #pragma unroll
        for (int mt = 0; mt < 2; mt++)
            #pragma unroll
            for (int aa = 0; aa < 2; aa++) {
                __half2 s0 = __hadd2(*(__half2*)&afr[mt][0][aa],
                                     *(__half2*)&afr[mt][0][aa + 2]);
                __half2 s1 = __hadd2(*(__half2*)&afr[mt][1][aa],
                                     *(__half2*)&afr[mt][1][aa + 2]);
                float2 f0 = __half22float2(s0);
                float2 f1 = __half22float2(s1);
                den4[mt][aa] += (f0.x + f0.y) + (f1.x + f1.y);
            }

        // ---- B fragments to regs ----
        uint32_t bq[2][4][4];
        #pragma unroll
        for (int kt = 0; kt < 2; kt++) {
            const uint32_t abase = sb + s * STAGE_B + STAGE_ADJ_B
                                   + (kt * 16 + ldsm_row) * 144 + ldsm_f * 16;
            #pragma unroll
            for (int p = 0; p < 4; p++)
                LDSM_X4_T(bq[kt][p][0], bq[kt][p][1], bq[kt][p][2], bq[kt][p][3],
                          abase + p * 32);
        }
        __syncthreads();   // all warps done with stage s

        // ---- prefetch tile it+3 into stage s ----
        if (it + 3 < NT) { PREFETCH(it + 3); } else { CP_COMMIT(); }

        // ---- 32 MMAs ----
        #pragma unroll
        for (int kt = 0; kt < 2; kt++)
            #pragma unroll
            for (int p = 0; p < 4; p++) {
                MMA_F16(acc[0][2 * p],     afr[0][kt], bq[kt][p][0], bq[kt][p][1]);
                MMA_F16(acc[0][2 * p + 1], afr[0][kt], bq[kt][p][2], bq[kt][p][3]);
                MMA_F16(acc[1][2 * p],     afr[1][kt], bq[kt][p][0], bq[kt][p][1]);
                MMA_F16(acc[1][2 * p + 1], afr[1][kt], bq[kt][p][2], bq[kt][p][3]);
            }
    }

    // ---- epilogue ----
    float* ob = g_acc[js];
    #pragma unroll
    for (int mt = 0; mt < 2; mt++) {
        const int ir = i_warp + mt * 16 + r0;
        #pragma unroll
        for (int nt = 0; nt < 8; nt++) {
            const int fc = nt * 8 + c0;
            *(float2*)&ob[(size_t)ir * FOUT + fc] =
                make_float2(acc[mt][nt][0], acc[mt][nt][1]);
            *(float2*)&ob[(size_t)(ir + 8) * FOUT + fc] =
                make_float2(acc[mt][nt][2], acc[mt][nt][3]);
        }
    }
    #pragma unroll
    for (int mt = 0; mt < 2; mt++)
        #pragma unroll
        for (int aa = 0; aa < 2; aa++) {
            float d = den4[mt][aa];
            d += __shfl_xor_sync(0xffffffffu, d, 1);
            d += __shfl_xor_sync(0xffffffffu, d, 2);
            if ((lane & 3) == 0)
                g_den[js][i_warp + mt * 16 + aa * 8 + r0] = d;
        }
}

// ============================================================
// Kernel C: combine partials, normalize, ELU.
// ============================================================
__global__ void __launch_bounds__(256) gat_final(float* __restrict__ out)
{
    const int idx = blockIdx.x * 256 + threadIdx.x;
    const int i = idx >> 6;
    float d = 0.f, v = 0.f;
    #pragma unroll
    for (int s = 0; s < JSPLIT; s++) {
        d += g_den[s][i];
        v += g_acc[s][idx];
    }
    float h = v / d;
    out[idx] = (h > 0.f) ? h : expm1f(h);
}

// ============================================================
extern "C" void kernel_launch(void* const* d_in, const int* in_sizes, int n_in,
                              void* d_out, int out_size)
{
    const float* x   = (const float*)d_in[0];
    const float* adj = (const float*)d_in[1];
    const float* W   = (const float*)d_in[2];
    const float* a   = (const float*)d_in[3];
    float* out = (float*)d_out;

    cudaFuncSetAttribute(gat_prep, cudaFuncAttributeMaxDynamicSharedMemorySize,
                         PREP_SMEM);
    cudaFuncSetAttribute(gat_attn, cudaFuncAttributeMaxDynamicSharedMemorySize,
                         SMEMB_BYTES);

    gat_prep<<<N / 64, 128, PREP_SMEM>>>(x, W, a);
    gat_attn<<<dim3(N / TI, JSPLIT), TI, SMEMB_BYTES>>>(adj);
    gat_final<<<(N * FOUT) / 256, 256>>>(out);
}

// round 15
// speedup vs baseline: 1.0390x; 1.0390x over previous
#include <cuda_runtime.h>
#include <cuda_fp16.h>
#include <cstdint>

// GAT layer, N=8192, Fin=128, Fout=64.
// inputs: x [N,128] f32, adj [N,N] f32 (0/1), W [128,64] f32, a [128,1] f32
// output: [N,64] f32

#define N      8192
#define FOUT   64
#define TI     128
#define TJ     32
#define JSPLIT 16
#define JRANGE (N / JSPLIT)     // 512
#define NT     (JRANGE / TJ)    // 16

#define ADJ_STR 40                        // floats per adj smem row (160 B)
#define STAGE_ADJ_B (TI * ADJ_STR * 4)    // 20480
#define STAGE_WH_B  (TJ * 72 * 2)         // 4608 (144B rows)
#define STAGE_B     (STAGE_ADJ_B + STAGE_WH_B)   // 25088
#define SMEMB_BYTES (3 * STAGE_B)         // 75264

// ---------------- device scratch ----------------
__device__ float2 g_E1P[N];
__device__ __half g_E2XH[N];
__device__ __half g_E2YH[N];
__device__ __half g_Wh_h[N * FOUT];          // Wh [j][f] fp16
__device__ float  g_acc[JSPLIT][N * FOUT];
__device__ float  g_den[JSPLIT][N];

// ---------------- helpers ----------------
#define CP_ASYNC16(dst, src) \
    asm volatile("cp.async.cg.shared.global [%0], [%1], 16;" :: "r"(dst), "l"(src))
#define CP_COMMIT() asm volatile("cp.async.commit_group;")
#define CP_WAIT2()  asm volatile("cp.async.wait_group 2;" ::: "memory")

#define LDSM_X4(d0, d1, d2, d3, addr)                                          \
    asm volatile("ldmatrix.sync.aligned.m8n8.x4.shared.b16 "                   \
                 "{%0,%1,%2,%3}, [%4];"                                        \
                 : "=r"(d0), "=r"(d1), "=r"(d2), "=r"(d3) : "r"(addr))
#define LDSM_X4_T(d0, d1, d2, d3, addr)                                        \
    asm volatile("ldmatrix.sync.aligned.m8n8.x4.trans.shared.b16 "             \
                 "{%0,%1,%2,%3}, [%4];"                                        \
                 : "=r"(d0), "=r"(d1), "=r"(d2), "=r"(d3) : "r"(addr))

#define MMA_F16(D, A, B0, B1)                                                 \
    asm("mma.sync.aligned.m16n8k16.row.col.f32.f16.f16.f32 "                  \
        "{%0,%1,%2,%3},{%4,%5,%6,%7},{%8,%9},{%0,%1,%2,%3};"                  \
        : "+f"((D)[0]), "+f"((D)[1]), "+f"((D)[2]), "+f"((D)[3])              \
        : "r"((A)[0]), "r"((A)[1]), "r"((A)[2]), "r"((A)[3]),                 \
          "r"(B0), "r"(B1))
#define MMA_F16R(D, A0, A1, A2, A3, B0, B1)                                   \
    asm("mma.sync.aligned.m16n8k16.row.col.f32.f16.f16.f32 "                  \
        "{%0,%1,%2,%3},{%4,%5,%6,%7},{%8,%9},{%0,%1,%2,%3};"                  \
        : "+f"((D)[0]), "+f"((D)[1]), "+f"((D)[2]), "+f"((D)[3])              \
        : "r"(A0), "r"(A1), "r"(A2), "r"(A3), "r"(B0), "r"(B1))

// ============================================================
// Kernel A: Wh = x@W via fp16 MMA (proven 6.7us R13 version).
// ============================================================
#define P_XH 0
#define P_WH 17408
#define P_A  (17408 + 18432)
#define PREP_SMEM (P_A + 512)

__global__ void __launch_bounds__(128) gat_prep(const float* __restrict__ x,
                                                const float* __restrict__ W,
                                                const float* __restrict__ a)
{
    extern __shared__ char psm[];
    __half* xh = (__half*)(psm + P_XH);
    __half* wh = (__half*)(psm + P_WH);
    float*  aS = (float*)(psm + P_A);

    const int t = threadIdx.x;
    const int row0 = blockIdx.x * 64;

    const float* xb = x + (size_t)row0 * 128;
    #pragma unroll
    for (int q = 0; q < 16; q++) {
        const int flat = (q * 128 + t) * 4;
        const int r = flat >> 7, c = flat & 127;
        float4 v = *(const float4*)&xb[flat];
        __half2 h0 = __floats2half2_rn(v.x, v.y);
        __half2 h1 = __floats2half2_rn(v.z, v.w);
        uint2 u = make_uint2(*(uint32_t*)&h0, *(uint32_t*)&h1);
        *(uint2*)&xh[r * 136 + c] = u;
    }
    #pragma unroll
    for (int q = 0; q < 16; q++) {
        const int flat = (q * 128 + t) * 4;
        const int k = flat >> 6, f = flat & 63;
        float4 v = *(const float4*)&W[flat];
        __half2 h0 = __floats2half2_rn(v.x, v.y);
        __half2 h1 = __floats2half2_rn(v.z, v.w);
        uint2 u = make_uint2(*(uint32_t*)&h0, *(uint32_t*)&h1);
        *(uint2*)&wh[k * 72 + f] = u;
    }
    if (t < 32) *(float4*)&aS[t * 4] = *(const float4*)&a[t * 4];
    __syncthreads();

    const int lane = t & 31, warp = t >> 5;
    const int rbase = warp * 16;
    const int mm = lane >> 3;
    const uint32_t sb = (uint32_t)__cvta_generic_to_shared(psm);

    const uint32_t A_base = sb + P_XH +
        ((rbase + (mm & 1) * 8 + (lane & 7)) * 136 + (mm >> 1) * 8) * 2;
    const int ldsm_row = (mm & 1) * 8 + (lane & 7);
    const int ldsm_f   = mm >> 1;
    const uint32_t B_base = sb + P_WH + ldsm_row * 144 + ldsm_f * 16;

    float c[8][4];
    #pragma unroll
    for (int nt = 0; nt < 8; nt++)
        #pragma unroll
        for (int e = 0; e < 4; e++) c[nt][e] = 0.f;

    #pragma unroll
    for (int kc = 0; kc < 8; kc++) {
        uint32_t A0, A1, A2, A3;
        LDSM_X4(A0, A1, A2, A3, A_base + kc * 32);
        #pragma unroll
        for (int p = 0; p < 4; p++) {
            uint32_t q0, q1, q2, q3;
            LDSM_X4_T(q0, q1, q2, q3, B_base + kc * 16 * 144 + p * 32);
            MMA_F16R(c[2 * p],     A0, A1, A2, A3, q0, q1);
            MMA_F16R(c[2 * p + 1], A0, A1, A2, A3, q2, q3);
        }
    }

    const int qq = lane & 3, r0 = lane >> 2;
    const int rowlo = row0 + rbase + r0;
    float p1lo = 0.f, p1hi = 0.f, p2lo = 0.f, p2hi = 0.f;
    #pragma unroll
    for (int nt = 0; nt < 8; nt++) {
        const int col = nt * 8 + 2 * qq;
        const float a1l = aS[col], a1h = aS[col + 1];
        const float a2l = aS[64 + col], a2h = aS[64 + col + 1];
        p1lo += c[nt][0] * a1l + c[nt][1] * a1h;
        p1hi += c[nt][2] * a1l + c[nt][3] * a1h;
        p2lo += c[nt][0] * a2l + c[nt][1] * a2h;
        p2hi += c[nt][2] * a2l + c[nt][3] * a2h;
        __half2 h0 = __floats2half2_rn(c[nt][0], c[nt][1]);
        __half2 h1 = __floats2half2_rn(c[nt][2], c[nt][3]);
        *(uint32_t*)&g_Wh_h[(size_t)rowlo * 64 + col]       = *(uint32_t*)&h0;
        *(uint32_t*)&g_Wh_h[(size_t)(rowlo + 8) * 64 + col] = *(uint32_t*)&h1;
    }
    p1lo += __shfl_xor_sync(0xffffffffu, p1lo, 1);
    p1lo += __shfl_xor_sync(0xffffffffu, p1lo, 2);
    p1hi += __shfl_xor_sync(0xffffffffu, p1hi, 1);
    p1hi += __shfl_xor_sync(0xffffffffu, p1hi, 2);
    p2lo += __shfl_xor_sync(0xffffffffu, p2lo, 1);
    p2lo += __shfl_xor_sync(0xffffffffu, p2lo, 2);
    p2hi += __shfl_xor_sync(0xffffffffu, p2hi, 1);
    p2hi += __shfl_xor_sync(0xffffffffu, p2hi, 2);

    if (qq == 0) {
        g_E1P[rowlo]      = make_float2(__expf(p1lo), __expf(0.2f * p1lo));
        g_E1P[rowlo + 8]  = make_float2(__expf(p1hi), __expf(0.2f * p1hi));
        g_E2XH[rowlo]     = __float2half(__expf(p2lo));
        g_E2YH[rowlo]     = __float2half(__expf(0.2f * p2lo));
        g_E2XH[rowlo + 8] = __float2half(__expf(p2hi));
        g_E2YH[rowlo + 8] = __float2half(__expf(0.2f * p2hi));
    }
}

// ============================================================
// Kernel B: i-split 8-warp version. grid (64, 16) x 256 threads, 2 blocks/SM
// (4 warps/SMSP). Warp w owns rows [i_base + w*16, +16): 16 MMAs/warp/tile.
// 3-stage cp.async ring (adj+Wh); den on ALU pipe.
// ============================================================
__global__ void __launch_bounds__(256, 2) gat_attn(const float* __restrict__ adj)
{
    extern __shared__ char smem[];
    const int t = threadIdx.x, lane = t & 31, warp = t >> 5;
    const int ib = blockIdx.x, js = blockIdx.y;
    const int i_base = ib * TI, i_warp = i_base + warp * 16;
    const int j0 = js * JRANGE;
    const int r0 = lane >> 2, c0 = (lane & 3) * 2;

    const uint32_t sb = (uint32_t)__cvta_generic_to_shared(smem);

    // staging maps (256 threads)
    // adj: thread t -> row t>>1, 64B half-row (t&1)
    const int ar = t >> 1, ah = (t & 1) * 4;
    const float* adj_base = adj + (size_t)(i_base + ar) * N + j0 + ah * 4;
    // Wh: thread t -> row t>>3, seg t&7 (one 16B chunk)
    const int wr = t >> 3, wsg = t & 7;
    const __half* wh_base = g_Wh_h + (size_t)(j0 + wr) * 64 + wsg * 8;

#define PREFETCH(tt)                                                           \
    do {                                                                       \
        const uint32_t st_ = sb + ((tt) % 3) * STAGE_B;                        \
        const float* as_ = adj_base + (tt) * TJ;                               \
        CP_ASYNC16(st_ + ar * (ADJ_STR * 4) + (ah + 0) * 16, as_ + 0);         \
        CP_ASYNC16(st_ + ar * (ADJ_STR * 4) + (ah + 1) * 16, as_ + 4);         \
        CP_ASYNC16(st_ + ar * (ADJ_STR * 4) + (ah + 2) * 16, as_ + 8);         \
        CP_ASYNC16(st_ + ar * (ADJ_STR * 4) + (ah + 3) * 16, as_ + 12);        \
        CP_ASYNC16(st_ + STAGE_ADJ_B + wr * 144 + wsg * 16,                    \
                   wh_base + (size_t)((tt) * TJ) * 64);                        \
        CP_COMMIT();                                                           \
    } while (0)

    // e1 fp16 splats (invariant): rows i_warp + aa*8 + r0
    __half2 e1x2[2], e1y2[2];
    #pragma unroll
    for (int aa = 0; aa < 2; aa++) {
        float2 e1f = g_E1P[i_warp + aa * 8 + r0];
        e1x2[aa] = __half2half2(__float2half(e1f.x));
        e1y2[aa] = __half2half2(__float2half(e1f.y));
    }

    float acc[8][4];
    #pragma unroll
    for (int nt = 0; nt < 8; nt++)
        #pragma unroll
        for (int e = 0; e < 4; e++) acc[nt][e] = 0.f;
    float den4[2] = {0.f, 0.f};

    // ldmatrix lane map (x4.trans)
    const int mm = lane >> 3;
    const int ldsm_row = (mm & 1) * 8 + (lane & 7);
    const int ldsm_f   = mm >> 1;

    PREFETCH(0); PREFETCH(1); PREFETCH(2);

    #pragma unroll 1
    for (int it = 0; it < NT; it++) {
        const int s = it % 3;
        const int jt = j0 + it * TJ;
        CP_WAIT2();
        __syncthreads();

        // ---- e2 fp16 pair loads (L1-hot) ----
        __half2 ex2[2][2], ey2[2][2];
        #pragma unroll
        for (int kt = 0; kt < 2; kt++)
            #pragma unroll
            for (int hh = 0; hh < 2; hh++) {
                const int jj = jt + kt * 16 + hh * 8 + c0;
                ex2[kt][hh] = *(const __half2*)&g_E2XH[jj];
                ey2[kt][hh] = *(const __half2*)&g_E2YH[jj];
            }

        // ---- A fragments (P) from smem adj ----
        const float* adjS = (const float*)(smem + s * STAGE_B);
        uint32_t afr[2][4];
        #pragma unroll
        for (int kt = 0; kt < 2; kt++)
            #pragma unroll
            for (int aa = 0; aa < 2; aa++)
                #pragma unroll
                for (int hh = 0; hh < 2; hh++) {
                    const int R = warp * 16 + aa * 8 + r0;
                    float2 ad = *(const float2*)&adjS[R * ADJ_STR +
                                                      kt * 16 + hh * 8 + c0];
                    __half2 ahv = __floats2half2_rn(ad.x, ad.y);
                    __half2 u  = __hmul2(e1x2[aa], ex2[kt][hh]);
                    __half2 v  = __hmul2(e1y2[aa], ey2[kt][hh]);
                    __half2 p  = __hmul2(__hmax2(u, v), ahv);
                    afr[kt][aa + 2 * hh] = *(uint32_t*)&p;
                }

        // ---- den on ALU pipe ----
        #pragma unroll
        for (int aa = 0; aa < 2; aa++) {
            __half2 s0 = __hadd2(*(__half2*)&afr[0][aa], *(__half2*)&afr[0][aa + 2]);
            __half2 s1 = __hadd2(*(__half2*)&afr[1][aa], *(__half2*)&afr[1][aa + 2]);
            float2 f0 = __half22float2(s0);
            float2 f1 = __half22float2(s1);
            den4[aa] += (f0.x + f0.y) + (f1.x + f1.y);
        }

        // ---- B fragments to regs ----
        uint32_t bq[2][4][4];
        #pragma unroll
        for (int kt = 0; kt < 2; kt++) {
            const uint32_t abase = sb + s * STAGE_B + STAGE_ADJ_B
                                   + (kt * 16 + ldsm_row) * 144 + ldsm_f * 16;
            #pragma unroll
            for (int p = 0; p < 4; p++)
                LDSM_X4_T(bq[kt][p][0], bq[kt][p][1], bq[kt][p][2], bq[kt][p][3],
                          abase + p * 32);
        }
        __syncthreads();   // all warps done with stage s

        // ---- prefetch tile it+3 into stage s ----
        if (it + 3 < NT) { PREFETCH(it + 3); } else { CP_COMMIT(); }

        // ---- 16 MMAs ----
        #pragma unroll
        for (int kt = 0; kt < 2; kt++)
            #pragma unroll
            for (int p = 0; p < 4; p++) {
                MMA_F16(acc[2 * p],     afr[kt], bq[kt][p][0], bq[kt][p][1]);
                MMA_F16(acc[2 * p + 1], afr[kt], bq[kt][p][2], bq[kt][p][3]);
            }
    }

    // ---- epilogue ----
    float* ob = g_acc[js];
    const int ir = i_warp + r0;
    #pragma unroll
    for (int nt = 0; nt < 8; nt++) {
        const int fc = nt * 8 + c0;
        *(float2*)&ob[(size_t)ir * FOUT + fc] =
            make_float2(acc[nt][0], acc[nt][1]);
        *(float2*)&ob[(size_t)(ir + 8) * FOUT + fc] =
            make_float2(acc[nt][2], acc[nt][3]);
    }
    #pragma unroll
    for (int aa = 0; aa < 2; aa++) {
        float d = den4[aa];
        d += __shfl_xor_sync(0xffffffffu, d, 1);
        d += __shfl_xor_sync(0xffffffffu, d, 2);
        if ((lane & 3) == 0)
            g_den[js][i_warp + aa * 8 + r0] = d;
    }
}

// ============================================================
// Kernel C: combine partials, normalize, ELU.
// ============================================================
__global__ void __launch_bounds__(256) gat_final(float* __restrict__ out)
{
    const int idx = blockIdx.x * 256 + threadIdx.x;
    const int i = idx >> 6;
    float d = 0.f, v = 0.f;
    #pragma unroll
    for (int s = 0; s < JSPLIT; s++) {
        d += g_den[s][i];
        v += g_acc[s][idx];
    }
    float h = v / d;
    out[idx] = (h > 0.f) ? h : expm1f(h);
}

// ============================================================
extern "C" void kernel_launch(void* const* d_in, const int* in_sizes, int n_in,
                              void* d_out, int out_size)
{
    const float* x   = (const float*)d_in[0];
    const float* adj = (const float*)d_in[1];
    const float* W   = (const float*)d_in[2];
    const float* a   = (const float*)d_in[3];
    float* out = (float*)d_out;

    cudaFuncSetAttribute(gat_prep, cudaFuncAttributeMaxDynamicSharedMemorySize,
                         PREP_SMEM);
    cudaFuncSetAttribute(gat_attn, cudaFuncAttributeMaxDynamicSharedMemorySize,
                         SMEMB_BYTES);

    gat_prep<<<N / 64, 128, PREP_SMEM>>>(x, W, a);
    gat_attn<<<dim3(N / TI, JSPLIT), 256, SMEMB_BYTES>>>(adj);
    gat_final<<<(N * FOUT) / 256, 256>>>(out);
}

// round 16
// speedup vs baseline: 1.3292x; 1.2793x over previous
#include <cuda_runtime.h>
#include <cuda_fp16.h>
#include <cstdint>

// GAT layer, N=8192, Fin=128, Fout=64.
// inputs: x [N,128] f32, adj [N,N] f32 (0/1), W [128,64] f32, a [128,1] f32
// output: [N,64] f32

#define N      8192
#define FOUT   64
#define TI     128
#define TJ     32
#define JSPLIT 16
#define JRANGE (N / JSPLIT)     // 512
#define NT     (JRANGE / TJ)    // 16

#define ADJ_STR 40                        // floats per adj smem row (160 B)
#define STAGE_ADJ_B (TI * ADJ_STR * 4)    // 20480
#define STAGE_WH_B  (TJ * 72 * 2)         // 4608 (144B rows)
#define STAGE_B     (STAGE_ADJ_B + STAGE_WH_B)   // 25088
#define SMEMB_BYTES (2 * STAGE_B)         // 50176 -> 4 blocks/SM

// ---------------- device scratch ----------------
__device__ float2 g_E1P[N];
__device__ __half g_E2XH[N];
__device__ __half g_E2YH[N];
__device__ __half g_Wh_h[N * FOUT];          // Wh [j][f] fp16
__device__ float  g_acc[JSPLIT][N * FOUT];
__device__ float  g_den[JSPLIT][N];

// ---------------- helpers ----------------
#define CP_ASYNC16(dst, src) \
    asm volatile("cp.async.cg.shared.global [%0], [%1], 16;" :: "r"(dst), "l"(src))
#define CP_COMMIT() asm volatile("cp.async.commit_group;")
#define CP_WAIT1()  asm volatile("cp.async.wait_group 1;" ::: "memory")

#define LDSM_X4(d0, d1, d2, d3, addr)                                          \
    asm volatile("ldmatrix.sync.aligned.m8n8.x4.shared.b16 "                   \
                 "{%0,%1,%2,%3}, [%4];"                                        \
                 : "=r"(d0), "=r"(d1), "=r"(d2), "=r"(d3) : "r"(addr))
#define LDSM_X4_T(d0, d1, d2, d3, addr)                                        \
    asm volatile("ldmatrix.sync.aligned.m8n8.x4.trans.shared.b16 "             \
                 "{%0,%1,%2,%3}, [%4];"                                        \
                 : "=r"(d0), "=r"(d1), "=r"(d2), "=r"(d3) : "r"(addr))

#define MMA_F16(D, A, B0, B1)                                                 \
    asm("mma.sync.aligned.m16n8k16.row.col.f32.f16.f16.f32 "                  \
        "{%0,%1,%2,%3},{%4,%5,%6,%7},{%8,%9},{%0,%1,%2,%3};"                  \
        : "+f"((D)[0]), "+f"((D)[1]), "+f"((D)[2]), "+f"((D)[3])              \
        : "r"((A)[0]), "r"((A)[1]), "r"((A)[2]), "r"((A)[3]),                 \
          "r"(B0), "r"(B1))
#define MMA_F16R(D, A0, A1, A2, A3, B0, B1)                                   \
    asm("mma.sync.aligned.m16n8k16.row.col.f32.f16.f16.f32 "                  \
        "{%0,%1,%2,%3},{%4,%5,%6,%7},{%8,%9},{%0,%1,%2,%3};"                  \
        : "+f"((D)[0]), "+f"((D)[1]), "+f"((D)[2]), "+f"((D)[3])              \
        : "r"(A0), "r"(A1), "r"(A2), "r"(A3), "r"(B0), "r"(B1))

// ============================================================
// Kernel A: Wh = x@W via fp16 MMA (proven 6.7us R13 version).
// ============================================================
#define P_XH 0
#define P_WH 17408
#define P_A  (17408 + 18432)
#define PREP_SMEM (P_A + 512)

__global__ void __launch_bounds__(128) gat_prep(const float* __restrict__ x,
                                                const float* __restrict__ W,
                                                const float* __restrict__ a)
{
    extern __shared__ char psm[];
    __half* xh = (__half*)(psm + P_XH);
    __half* wh = (__half*)(psm + P_WH);
    float*  aS = (float*)(psm + P_A);

    const int t = threadIdx.x;
    const int row0 = blockIdx.x * 64;

    const float* xb = x + (size_t)row0 * 128;
    #pragma unroll
    for (int q = 0; q < 16; q++) {
        const int flat = (q * 128 + t) * 4;
        const int r = flat >> 7, c = flat & 127;
        float4 v = *(const float4*)&xb[flat];
        __half2 h0 = __floats2half2_rn(v.x, v.y);
        __half2 h1 = __floats2half2_rn(v.z, v.w);
        uint2 u = make_uint2(*(uint32_t*)&h0, *(uint32_t*)&h1);
        *(uint2*)&xh[r * 136 + c] = u;
    }
    #pragma unroll
    for (int q = 0; q < 16; q++) {
        const int flat = (q * 128 + t) * 4;
        const int k = flat >> 6, f = flat & 63;
        float4 v = *(const float4*)&W[flat];
        __half2 h0 = __floats2half2_rn(v.x, v.y);
        __half2 h1 = __floats2half2_rn(v.z, v.w);
        uint2 u = make_uint2(*(uint32_t*)&h0, *(uint32_t*)&h1);
        *(uint2*)&wh[k * 72 + f] = u;
    }
    if (t < 32) *(float4*)&aS[t * 4] = *(const float4*)&a[t * 4];
    __syncthreads();

    const int lane = t & 31, warp = t >> 5;
    const int rbase = warp * 16;
    const int mm = lane >> 3;
    const uint32_t sb = (uint32_t)__cvta_generic_to_shared(psm);

    const uint32_t A_base = sb + P_XH +
        ((rbase + (mm & 1) * 8 + (lane & 7)) * 136 + (mm >> 1) * 8) * 2;
    const int ldsm_row = (mm & 1) * 8 + (lane & 7);
    const int ldsm_f   = mm >> 1;
    const uint32_t B_base = sb + P_WH + ldsm_row * 144 + ldsm_f * 16;

    float c[8][4];
    #pragma unroll
    for (int nt = 0; nt < 8; nt++)
        #pragma unroll
        for (int e = 0; e < 4; e++) c[nt][e] = 0.f;

    #pragma unroll
    for (int kc = 0; kc < 8; kc++) {
        uint32_t A0, A1, A2, A3;
        LDSM_X4(A0, A1, A2, A3, A_base + kc * 32);
        #pragma unroll
        for (int p = 0; p < 4; p++) {
            uint32_t q0, q1, q2, q3;
            LDSM_X4_T(q0, q1, q2, q3, B_base + kc * 16 * 144 + p * 32);
            MMA_F16R(c[2 * p],     A0, A1, A2, A3, q0, q1);
            MMA_F16R(c[2 * p + 1], A0, A1, A2, A3, q2, q3);
        }
    }

    const int qq = lane & 3, r0 = lane >> 2;
    const int rowlo = row0 + rbase + r0;
    float p1lo = 0.f, p1hi = 0.f, p2lo = 0.f, p2hi = 0.f;
    #pragma unroll
    for (int nt = 0; nt < 8; nt++) {
        const int col = nt * 8 + 2 * qq;
        const float a1l = aS[col], a1h = aS[col + 1];
        const float a2l = aS[64 + col], a2h = aS[64 + col + 1];
        p1lo += c[nt][0] * a1l + c[nt][1] * a1h;
        p1hi += c[nt][2] * a1l + c[nt][3] * a1h;
        p2lo += c[nt][0] * a2l + c[nt][1] * a2h;
        p2hi += c[nt][2] * a2l + c[nt][3] * a2h;
        __half2 h0 = __floats2half2_rn(c[nt][0], c[nt][1]);
        __half2 h1 = __floats2half2_rn(c[nt][2], c[nt][3]);
        *(uint32_t*)&g_Wh_h[(size_t)rowlo * 64 + col]       = *(uint32_t*)&h0;
        *(uint32_t*)&g_Wh_h[(size_t)(rowlo + 8) * 64 + col] = *(uint32_t*)&h1;
    }
    p1lo += __shfl_xor_sync(0xffffffffu, p1lo, 1);
    p1lo += __shfl_xor_sync(0xffffffffu, p1lo, 2);
    p1hi += __shfl_xor_sync(0xffffffffu, p1hi, 1);
    p1hi += __shfl_xor_sync(0xffffffffu, p1hi, 2);
    p2lo += __shfl_xor_sync(0xffffffffu, p2lo, 1);
    p2lo += __shfl_xor_sync(0xffffffffu, p2lo, 2);
    p2hi += __shfl_xor_sync(0xffffffffu, p2hi, 1);
    p2hi += __shfl_xor_sync(0xffffffffu, p2hi, 2);

    if (qq == 0) {
        g_E1P[rowlo]      = make_float2(__expf(p1lo), __expf(0.2f * p1lo));
        g_E1P[rowlo + 8]  = make_float2(__expf(p1hi), __expf(0.2f * p1hi));
        g_E2XH[rowlo]     = __float2half(__expf(p2lo));
        g_E2YH[rowlo]     = __float2half(__expf(0.2f * p2lo));
        g_E2XH[rowlo + 8] = __float2half(__expf(p2hi));
        g_E2YH[rowlo + 8] = __float2half(__expf(0.2f * p2hi));
    }
}

// ============================================================
// Kernel B: 2-stage cp.async ring + fp16 MMA; den on ALU pipe.
// grid (64, 16) x 128 threads (4 warps), 4 blocks/SM (4 warps/SMSP).
// Warp w owns rows [i_base + w*32, +32): 32 MMAs/warp/tile.
// ============================================================
__global__ void __launch_bounds__(128, 4) gat_attn(const float* __restrict__ adj)
{
    extern __shared__ char smem[];
    const int t = threadIdx.x, lane = t & 31, warp = t >> 5;
    const int ib = blockIdx.x, js = blockIdx.y;
    const int i_base = ib * TI, i_warp = i_base + warp * 32;
    const int j0 = js * JRANGE;
    const int r0 = lane >> 2, c0 = (lane & 3) * 2;

    const uint32_t sb = (uint32_t)__cvta_generic_to_shared(smem);

    // staging maps (fully coalesced 128B chunks)
    const int arow = t >> 3, aseg = t & 7;
    const float* adj_base = adj + (size_t)(i_base + arow) * N + j0 + aseg * 4;
    const __half* wh_base = g_Wh_h + (size_t)(j0 + arow) * 64 + aseg * 8;

#define PREFETCH(tt)                                                           \
    do {                                                                       \
        const uint32_t st_ = sb + ((tt) & 1) * STAGE_B;                        \
        const float* as_ = adj_base + (tt) * TJ;                               \
        _Pragma("unroll")                                                      \
        for (int q_ = 0; q_ < 8; q_++)                                         \
            CP_ASYNC16(st_ + (q_ * 16 + arow) * (ADJ_STR * 4) + aseg * 16,     \
                       as_ + (size_t)(q_ * 16) * N);                           \
        const uint32_t wst_ = st_ + STAGE_ADJ_B;                               \
        const __half* ws_ = wh_base + (size_t)((tt) * TJ) * 64;                \
        CP_ASYNC16(wst_ + arow * 144 + aseg * 16, ws_);                        \
        CP_ASYNC16(wst_ + (16 + arow) * 144 + aseg * 16, ws_ + 16 * 64);       \
        CP_COMMIT();                                                           \
    } while (0)

    // e1 fp16 splats (invariant)
    __half2 e1x2[2][2], e1y2[2][2];
    #pragma unroll
    for (int mt = 0; mt < 2; mt++)
        #pragma unroll
        for (int aa = 0; aa < 2; aa++) {
            float2 e1f = g_E1P[i_warp + mt * 16 + aa * 8 + r0];
            e1x2[mt][aa] = __half2half2(__float2half(e1f.x));
            e1y2[mt][aa] = __half2half2(__float2half(e1f.y));
        }

    float acc[2][8][4];
    #pragma unroll
    for (int mt = 0; mt < 2; mt++)
        #pragma unroll
        for (int nt = 0; nt < 8; nt++)
            #pragma unroll
            for (int e = 0; e < 4; e++) acc[mt][nt][e] = 0.f;
    float den4[2][2] = {{0.f, 0.f}, {0.f, 0.f}};

    // ldmatrix lane map (x4.trans)
    const int mm = lane >> 3;
    const int ldsm_row = (mm & 1) * 8 + (lane & 7);
    const int ldsm_f   = mm >> 1;

    PREFETCH(0); PREFETCH(1);

    #pragma unroll 1
    for (int it = 0; it < NT; it++) {
        const int s = it & 1;
        const int jt = j0 + it * TJ;
        CP_WAIT1();
        __syncthreads();

        // ---- e2 fp16 pair loads (L1-hot) ----
        __half2 ex2[2][2], ey2[2][2];
        #pragma unroll
        for (int kt = 0; kt < 2; kt++)
            #pragma unroll
            for (int hh = 0; hh < 2; hh++) {
                const int jj = jt + kt * 16 + hh * 8 + c0;
                ex2[kt][hh] = *(const __half2*)&g_E2XH[jj];
                ey2[kt][hh] = *(const __half2*)&g_E2YH[jj];
            }

        // ---- A fragments (P) from smem adj ----
        const float* adjS = (const float*)(smem + s * STAGE_B);
        uint32_t afr[2][2][4];
        #pragma unroll
        for (int mt = 0; mt < 2; mt++)
            #pragma unroll
            for (int kt = 0; kt < 2; kt++)
                #pragma unroll
                for (int aa = 0; aa < 2; aa++)
                    #pragma unroll
                    for (int hh = 0; hh < 2; hh++) {
                        const int R = warp * 32 + mt * 16 + aa * 8 + r0;
                        float2 ad = *(const float2*)&adjS[R * ADJ_STR +
                                                          kt * 16 + hh * 8 + c0];
                        __half2 ah = __floats2half2_rn(ad.x, ad.y);
                        __half2 u  = __hmul2(e1x2[mt][aa], ex2[kt][hh]);
                        __half2 v  = __hmul2(e1y2[mt][aa], ey2[kt][hh]);
                        __half2 p  = __hmul2(__hmax2(u, v), ah);
                        afr[mt][kt][aa + 2 * hh] = *(uint32_t*)&p;
                    }

        // ---- den on ALU pipe (same rounded p values) ----
        #pragma unroll
        for (int mt = 0; mt < 2; mt++)
            #pragma unroll
            for (int aa = 0; aa < 2; aa++) {
                __half2 s0 = __hadd2(*(__half2*)&afr[mt][0][aa],
                                     *(__half2*)&afr[mt][0][aa + 2]);
                __half2 s1 = __hadd2(*(__half2*)&afr[mt][1][aa],
                                     *(__half2*)&afr[mt][1][aa + 2]);
                float2 f0 = __half22float2(s0);
                float2 f1 = __half22float2(s1);
                den4[mt][aa] += (f0.x + f0.y) + (f1.x + f1.y);
            }

        // ---- B fragments to regs ----
        uint32_t bq[2][4][4];
        #pragma unroll
        for (int kt = 0; kt < 2; kt++) {
            const uint32_t abase = sb + s * STAGE_B + STAGE_ADJ_B
                                   + (kt * 16 + ldsm_row) * 144 + ldsm_f * 16;
            #pragma unroll
            for (int p = 0; p < 4; p++)
                LDSM_X4_T(bq[kt][p][0], bq[kt][p][1], bq[kt][p][2], bq[kt][p][3],
                          abase + p * 32);
        }
        __syncthreads();   // all warps done with stage s

        // ---- prefetch tile it+2 into stage s ----
        if (it + 2 < NT) { PREFETCH(it + 2); } else { CP_COMMIT(); }

        // ---- 32 MMAs ----
        #pragma unroll
        for (int kt = 0; kt < 2; kt++)
            #pragma unroll
            for (int p = 0; p < 4; p++) {
                MMA_F16(acc[0][2 * p],     afr[0][kt], bq[kt][p][0], bq[kt][p][1]);
                MMA_F16(acc[0][2 * p + 1], afr[0][kt], bq[kt][p][2], bq[kt][p][3]);
                MMA_F16(acc[1][2 * p],     afr[1][kt], bq[kt][p][0], bq[kt][p][1]);
                MMA_F16(acc[1][2 * p + 1], afr[1][kt], bq[kt][p][2], bq[kt][p][3]);
            }
    }

    // ---- epilogue ----
    float* ob = g_acc[js];
    #pragma unroll
    for (int mt = 0; mt < 2; mt++) {
        const int ir = i_warp + mt * 16 + r0;
        #pragma unroll
        for (int nt = 0; nt < 8; nt++) {
            const int fc = nt * 8 + c0;
            *(float2*)&ob[(size_t)ir * FOUT + fc] =
                make_float2(acc[mt][nt][0], acc[mt][nt][1]);
            *(float2*)&ob[(size_t)(ir + 8) * FOUT + fc] =
                make_float2(acc[mt][nt][2], acc[mt][nt][3]);
        }
    }
    #pragma unroll
    for (int mt = 0; mt < 2; mt++)
        #pragma unroll
        for (int aa = 0; aa < 2; aa++) {
            float d = den4[mt][aa];
            d += __shfl_xor_sync(0xffffffffu, d, 1);
            d += __shfl_xor_sync(0xffffffffu, d, 2);
            if ((lane & 3) == 0)
                g_den[js][i_warp + mt * 16 + aa * 8 + r0] = d;
        }
}

// ============================================================
// Kernel C: combine partials, normalize, ELU.
// ============================================================
__global__ void __launch_bounds__(256) gat_final(float* __restrict__ out)
{
    const int idx = blockIdx.x * 256 + threadIdx.x;
    const int i = idx >> 6;
    float d = 0.f, v = 0.f;
    #pragma unroll
    for (int s = 0; s < JSPLIT; s++) {
        d += g_den[s][i];
        v += g_acc[s][idx];
    }
    float h = v / d;
    out[idx] = (h > 0.f) ? h : expm1f(h);
}

// ============================================================
extern "C" void kernel_launch(void* const* d_in, const int* in_sizes, int n_in,
                              void* d_out, int out_size)
{
    const float* x   = (const float*)d_in[0];
    const float* adj = (const float*)d_in[1];
    const float* W   = (const float*)d_in[2];
    const float* a   = (const float*)d_in[3];
    float* out = (float*)d_out;

    cudaFuncSetAttribute(gat_prep, cudaFuncAttributeMaxDynamicSharedMemorySize,
                         PREP_SMEM);
    cudaFuncSetAttribute(gat_attn, cudaFuncAttributeMaxDynamicSharedMemorySize,
                         SMEMB_BYTES);

    gat_prep<<<N / 64, 128, PREP_SMEM>>>(x, W, a);
    gat_attn<<<dim3(N / TI, JSPLIT), TI, SMEMB_BYTES>>>(adj);
    gat_final<<<(N * FOUT) / 256, 256>>>(out);
}

// round 17
// speedup vs baseline: 1.3375x; 1.0063x over previous
#include <cuda_runtime.h>
#include <cuda_fp16.h>
#include <cstdint>

// GAT layer, N=8192, Fin=128, Fout=64.
// inputs: x [N,128] f32, adj [N,N] f32 (0/1), W [128,64] f32, a [128,1] f32
// output: [N,64] f32

#define N      8192
#define FOUT   64
#define TI     128
#define TJ     32
#define JSPLIT 16
#define JRANGE (N / JSPLIT)     // 512
#define NT     (JRANGE / TJ)    // 16

#define ADJ_STR 40                        // floats per adj smem row (160 B)
#define STAGE_ADJ_B (TI * ADJ_STR * 4)    // 20480
#define STAGE_WH_B  (TJ * 72 * 2)         // 4608 (144B rows)
#define STAGE_B     (STAGE_ADJ_B + STAGE_WH_B)   // 25088
#define SMEMB_BYTES (2 * STAGE_B)         // 50176 -> 4 blocks/SM

// ---------------- device scratch ----------------
__device__ float2 g_E1P[N];
__device__ __half g_E2XH[N];
__device__ __half g_E2YH[N];
__device__ __half g_Wh_h[N * FOUT];          // Wh [j][f] fp16
__device__ float  g_acc[JSPLIT][N * FOUT];
__device__ float  g_den[JSPLIT][N];

// ---------------- helpers ----------------
#define CP_ASYNC16(dst, src) \
    asm volatile("cp.async.cg.shared.global [%0], [%1], 16;" :: "r"(dst), "l"(src))
#define CP_COMMIT() asm volatile("cp.async.commit_group;")
#define CP_WAIT1()  asm volatile("cp.async.wait_group 1;" ::: "memory")

#define LDSM_X4(d0, d1, d2, d3, addr)                                          \
    asm volatile("ldmatrix.sync.aligned.m8n8.x4.shared.b16 "                   \
                 "{%0,%1,%2,%3}, [%4];"                                        \
                 : "=r"(d0), "=r"(d1), "=r"(d2), "=r"(d3) : "r"(addr))
#define LDSM_X4_T(d0, d1, d2, d3, addr)                                        \
    asm volatile("ldmatrix.sync.aligned.m8n8.x4.trans.shared.b16 "             \
                 "{%0,%1,%2,%3}, [%4];"                                        \
                 : "=r"(d0), "=r"(d1), "=r"(d2), "=r"(d3) : "r"(addr))

#define MMA_F16(D, A, B0, B1)                                                 \
    asm("mma.sync.aligned.m16n8k16.row.col.f32.f16.f16.f32 "                  \
        "{%0,%1,%2,%3},{%4,%5,%6,%7},{%8,%9},{%0,%1,%2,%3};"                  \
        : "+f"((D)[0]), "+f"((D)[1]), "+f"((D)[2]), "+f"((D)[3])              \
        : "r"((A)[0]), "r"((A)[1]), "r"((A)[2]), "r"((A)[3]),                 \
          "r"(B0), "r"(B1))
#define MMA_F16R(D, A0, A1, A2, A3, B0, B1)                                   \
    asm("mma.sync.aligned.m16n8k16.row.col.f32.f16.f16.f32 "                  \
        "{%0,%1,%2,%3},{%4,%5,%6,%7},{%8,%9},{%0,%1,%2,%3};"                  \
        : "+f"((D)[0]), "+f"((D)[1]), "+f"((D)[2]), "+f"((D)[3])              \
        : "r"(A0), "r"(A1), "r"(A2), "r"(A3), "r"(B0), "r"(B1))

// ============================================================
// Kernel A: Wh = x@W via fp16 MMA.
// 256 blocks x 64 threads (2 warps x 16 rows = 32 rows/block).
// smem: xh [32][136 halves] | wh [128][72 halves] | aS f32[128]
// ============================================================
#define P_XH 0
#define P_WH 8704
#define P_A  (8704 + 18432)
#define PREP_SMEM (P_A + 512)   // 27648

__global__ void __launch_bounds__(64) gat_prep(const float* __restrict__ x,
                                               const float* __restrict__ W,
                                               const float* __restrict__ a)
{
    extern __shared__ char psm[];
    __half* xh = (__half*)(psm + P_XH);
    __half* wh = (__half*)(psm + P_WH);
    float*  aS = (float*)(psm + P_A);

    const int t = threadIdx.x;
    const int row0 = blockIdx.x * 32;

    // stage x tile (32x128 f32 -> fp16)
    const float* xb = x + (size_t)row0 * 128;
    #pragma unroll
    for (int q = 0; q < 16; q++) {
        const int flat = (q * 64 + t) * 4;
        const int r = flat >> 7, c = flat & 127;
        float4 v = *(const float4*)&xb[flat];
        __half2 h0 = __floats2half2_rn(v.x, v.y);
        __half2 h1 = __floats2half2_rn(v.z, v.w);
        uint2 u = make_uint2(*(uint32_t*)&h0, *(uint32_t*)&h1);
        *(uint2*)&xh[r * 136 + c] = u;
    }
    // stage W (128x64 f32 -> fp16)
    #pragma unroll
    for (int q = 0; q < 32; q++) {
        const int flat = (q * 64 + t) * 4;
        const int k = flat >> 6, f = flat & 63;
        float4 v = *(const float4*)&W[flat];
        __half2 h0 = __floats2half2_rn(v.x, v.y);
        __half2 h1 = __floats2half2_rn(v.z, v.w);
        uint2 u = make_uint2(*(uint32_t*)&h0, *(uint32_t*)&h1);
        *(uint2*)&wh[k * 72 + f] = u;
    }
    if (t < 32) *(float4*)&aS[t * 4] = *(const float4*)&a[t * 4];
    __syncthreads();

    const int lane = t & 31, warp = t >> 5;
    const int rbase = warp * 16;
    const int mm = lane >> 3;
    const uint32_t sb = (uint32_t)__cvta_generic_to_shared(psm);

    const uint32_t A_base = sb + P_XH +
        ((rbase + (mm & 1) * 8 + (lane & 7)) * 136 + (mm >> 1) * 8) * 2;
    const int ldsm_row = (mm & 1) * 8 + (lane & 7);
    const int ldsm_f   = mm >> 1;
    const uint32_t B_base = sb + P_WH + ldsm_row * 144 + ldsm_f * 16;

    float c[8][4];
    #pragma unroll
    for (int nt = 0; nt < 8; nt++)
        #pragma unroll
        for (int e = 0; e < 4; e++) c[nt][e] = 0.f;

    #pragma unroll
    for (int kc = 0; kc < 8; kc++) {
        uint32_t A0, A1, A2, A3;
        LDSM_X4(A0, A1, A2, A3, A_base + kc * 32);
        #pragma unroll
        for (int p = 0; p < 4; p++) {
            uint32_t q0, q1, q2, q3;
            LDSM_X4_T(q0, q1, q2, q3, B_base + kc * 16 * 144 + p * 32);
            MMA_F16R(c[2 * p],     A0, A1, A2, A3, q0, q1);
            MMA_F16R(c[2 * p + 1], A0, A1, A2, A3, q2, q3);
        }
    }

    const int qq = lane & 3, r0 = lane >> 2;
    const int rowlo = row0 + rbase + r0;
    float p1lo = 0.f, p1hi = 0.f, p2lo = 0.f, p2hi = 0.f;
    #pragma unroll
    for (int nt = 0; nt < 8; nt++) {
        const int col = nt * 8 + 2 * qq;
        const float a1l = aS[col], a1h = aS[col + 1];
        const float a2l = aS[64 + col], a2h = aS[64 + col + 1];
        p1lo += c[nt][0] * a1l + c[nt][1] * a1h;
        p1hi += c[nt][2] * a1l + c[nt][3] * a1h;
        p2lo += c[nt][0] * a2l + c[nt][1] * a2h;
        p2hi += c[nt][2] * a2l + c[nt][3] * a2h;
        __half2 h0 = __floats2half2_rn(c[nt][0], c[nt][1]);
        __half2 h1 = __floats2half2_rn(c[nt][2], c[nt][3]);
        *(uint32_t*)&g_Wh_h[(size_t)rowlo * 64 + col]       = *(uint32_t*)&h0;
        *(uint32_t*)&g_Wh_h[(size_t)(rowlo + 8) * 64 + col] = *(uint32_t*)&h1;
    }
    p1lo += __shfl_xor_sync(0xffffffffu, p1lo, 1);
    p1lo += __shfl_xor_sync(0xffffffffu, p1lo, 2);
    p1hi += __shfl_xor_sync(0xffffffffu, p1hi, 1);
    p1hi += __shfl_xor_sync(0xffffffffu, p1hi, 2);
    p2lo += __shfl_xor_sync(0xffffffffu, p2lo, 1);
    p2lo += __shfl_xor_sync(0xffffffffu, p2lo, 2);
    p2hi += __shfl_xor_sync(0xffffffffu, p2hi, 1);
    p2hi += __shfl_xor_sync(0xffffffffu, p2hi, 2);

    if (qq == 0) {
        g_E1P[rowlo]      = make_float2(__expf(p1lo), __expf(0.2f * p1lo));
        g_E1P[rowlo + 8]  = make_float2(__expf(p1hi), __expf(0.2f * p1hi));
        g_E2XH[rowlo]     = __float2half(__expf(p2lo));
        g_E2YH[rowlo]     = __float2half(__expf(0.2f * p2lo));
        g_E2XH[rowlo + 8] = __float2half(__expf(p2hi));
        g_E2YH[rowlo + 8] = __float2half(__expf(0.2f * p2hi));
    }
}

// ============================================================
// Kernel B: 2-stage cp.async ring + fp16 MMA; den on ALU pipe.
// grid (64, 16) x 128 threads (4 warps), 4 blocks/SM. (82.0us R16 version)
// ============================================================
__global__ void __launch_bounds__(128, 4) gat_attn(const float* __restrict__ adj)
{
    extern __shared__ char smem[];
    const int t = threadIdx.x, lane = t & 31, warp = t >> 5;
    const int ib = blockIdx.x, js = blockIdx.y;
    const int i_base = ib * TI, i_warp = i_base + warp * 32;
    const int j0 = js * JRANGE;
    const int r0 = lane >> 2, c0 = (lane & 3) * 2;

    const uint32_t sb = (uint32_t)__cvta_generic_to_shared(smem);

    const int arow = t >> 3, aseg = t & 7;
    const float* adj_base = adj + (size_t)(i_base + arow) * N + j0 + aseg * 4;
    const __half* wh_base = g_Wh_h + (size_t)(j0 + arow) * 64 + aseg * 8;

#define PREFETCH(tt)                                                           \
    do {                                                                       \
        const uint32_t st_ = sb + ((tt) & 1) * STAGE_B;                        \
        const float* as_ = adj_base + (tt) * TJ;                               \
        _Pragma("unroll")                                                      \
        for (int q_ = 0; q_ < 8; q_++)                                         \
            CP_ASYNC16(st_ + (q_ * 16 + arow) * (ADJ_STR * 4) + aseg * 16,     \
                       as_ + (size_t)(q_ * 16) * N);                           \
        const uint32_t wst_ = st_ + STAGE_ADJ_B;                               \
        const __half* ws_ = wh_base + (size_t)((tt) * TJ) * 64;                \
        CP_ASYNC16(wst_ + arow * 144 + aseg * 16, ws_);                        \
        CP_ASYNC16(wst_ + (16 + arow) * 144 + aseg * 16, ws_ + 16 * 64);       \
        CP_COMMIT();                                                           \
    } while (0)

    __half2 e1x2[2][2], e1y2[2][2];
    #pragma unroll
    for (int mt = 0; mt < 2; mt++)
        #pragma unroll
        for (int aa = 0; aa < 2; aa++) {
            float2 e1f = g_E1P[i_warp + mt * 16 + aa * 8 + r0];
            e1x2[mt][aa] = __half2half2(__float2half(e1f.x));
            e1y2[mt][aa] = __half2half2(__float2half(e1f.y));
        }

    float acc[2][8][4];
    #pragma unroll
    for (int mt = 0; mt < 2; mt++)
        #pragma unroll
        for (int nt = 0; nt < 8; nt++)
            #pragma unroll
            for (int e = 0; e < 4; e++) acc[mt][nt][e] = 0.f;
    float den4[2][2] = {{0.f, 0.f}, {0.f, 0.f}};

    const int mm = lane >> 3;
    const int ldsm_row = (mm & 1) * 8 + (lane & 7);
    const int ldsm_f   = mm >> 1;

    PREFETCH(0); PREFETCH(1);

    #pragma unroll 1
    for (int it = 0; it < NT; it++) {
        const int s = it & 1;
        const int jt = j0 + it * TJ;
        CP_WAIT1();
        __syncthreads();

        __half2 ex2[2][2], ey2[2][2];
        #pragma unroll
        for (int kt = 0; kt < 2; kt++)
            #pragma unroll
            for (int hh = 0; hh < 2; hh++) {
                const int jj = jt + kt * 16 + hh * 8 + c0;
                ex2[kt][hh] = *(const __half2*)&g_E2XH[jj];
                ey2[kt][hh] = *(const __half2*)&g_E2YH[jj];
            }

        const float* adjS = (const float*)(smem + s * STAGE_B);
        uint32_t afr[2][2][4];
        #pragma unroll
        for (int mt = 0; mt < 2; mt++)
            #pragma unroll
            for (int kt = 0; kt < 2; kt++)
                #pragma unroll
                for (int aa = 0; aa < 2; aa++)
                    #pragma unroll
                    for (int hh = 0; hh < 2; hh++) {
                        const int R = warp * 32 + mt * 16 + aa * 8 + r0;
                        float2 ad = *(const float2*)&adjS[R * ADJ_STR +
                                                          kt * 16 + hh * 8 + c0];
                        __half2 ah = __floats2half2_rn(ad.x, ad.y);
                        __half2 u  = __hmul2(e1x2[mt][aa], ex2[kt][hh]);
                        __half2 v  = __hmul2(e1y2[mt][aa], ey2[kt][hh]);
                        __half2 p  = __hmul2(__hmax2(u, v), ah);
                        afr[mt][kt][aa + 2 * hh] = *(uint32_t*)&p;
                    }

        #pragma unroll
        for (int mt = 0; mt < 2; mt++)
            #pragma unroll
            for (int aa = 0; aa < 2; aa++) {
                __half2 s0 = __hadd2(*(__half2*)&afr[mt][0][aa],
                                     *(__half2*)&afr[mt][0][aa + 2]);
                __half2 s1 = __hadd2(*(__half2*)&afr[mt][1][aa],
                                     *(__half2*)&afr[mt][1][aa + 2]);
                float2 f0 = __half22float2(s0);
                float2 f1 = __half22float2(s1);
                den4[mt][aa] += (f0.x + f0.y) + (f1.x + f1.y);
            }

        uint32_t bq[2][4][4];
        #pragma unroll
        for (int kt = 0; kt < 2; kt++) {
            const uint32_t abase = sb + s * STAGE_B + STAGE_ADJ_B
                                   + (kt * 16 + ldsm_row) * 144 + ldsm_f * 16;
            #pragma unroll
            for (int p = 0; p < 4; p++)
                LDSM_X4_T(bq[kt][p][0], bq[kt][p][1], bq[kt][p][2], bq[kt][p][3],
                          abase + p * 32);
        }
        __syncthreads();

        if (it + 2 < NT) { PREFETCH(it + 2); } else { CP_COMMIT(); }

        #pragma unroll
        for (int kt = 0; kt < 2; kt++)
            #pragma unroll
            for (int p = 0; p < 4; p++) {
                MMA_F16(acc[0][2 * p],     afr[0][kt], bq[kt][p][0], bq[kt][p][1]);
                MMA_F16(acc[0][2 * p + 1], afr[0][kt], bq[kt][p][2], bq[kt][p][3]);
                MMA_F16(acc[1][2 * p],     afr[1][kt], bq[kt][p][0], bq[kt][p][1]);
                MMA_F16(acc[1][2 * p + 1], afr[1][kt], bq[kt][p][2], bq[kt][p][3]);
            }
    }

    float* ob = g_acc[js];
    #pragma unroll
    for (int mt = 0; mt < 2; mt++) {
        const int ir = i_warp + mt * 16 + r0;
        #pragma unroll
        for (int nt = 0; nt < 8; nt++) {
            const int fc = nt * 8 + c0;
            *(float2*)&ob[(size_t)ir * FOUT + fc] =
                make_float2(acc[mt][nt][0], acc[mt][nt][1]);
            *(float2*)&ob[(size_t)(ir + 8) * FOUT + fc] =
                make_float2(acc[mt][nt][2], acc[mt][nt][3]);
        }
    }
    #pragma unroll
    for (int mt = 0; mt < 2; mt++)
        #pragma unroll
        for (int aa = 0; aa < 2; aa++) {
            float d = den4[mt][aa];
            d += __shfl_xor_sync(0xffffffffu, d, 1);
            d += __shfl_xor_sync(0xffffffffu, d, 2);
            if ((lane & 3) == 0)
                g_den[js][i_warp + mt * 16 + aa * 8 + r0] = d;
        }
}

// ============================================================
// Kernel C: combine partials (float4), normalize, ELU.
// grid 512 x 256 threads; 4 consecutive f-elements per thread.
// ============================================================
__global__ void __launch_bounds__(256) gat_final(float* __restrict__ out)
{
    const int idx4 = (blockIdx.x * 256 + threadIdx.x) * 4;   // < N*FOUT
    const int i = idx4 >> 6;
    float d = 0.f;
    float4 v = make_float4(0.f, 0.f, 0.f, 0.f);
    #pragma unroll
    for (int s = 0; s < JSPLIT; s++) {
        d += g_den[s][i];
        float4 u = *(const float4*)&g_acc[s][idx4];
        v.x += u.x; v.y += u.y; v.z += u.z; v.w += u.w;
    }
    const float inv = 1.f / d;
    float4 o;
    float h;
    h = v.x * inv; o.x = (h > 0.f) ? h : expm1f(h);
    h = v.y * inv; o.y = (h > 0.f) ? h : expm1f(h);
    h = v.z * inv; o.z = (h > 0.f) ? h : expm1f(h);
    h = v.w * inv; o.w = (h > 0.f) ? h : expm1f(h);
    *(float4*)&out[idx4] = o;
}

// ============================================================
extern "C" void kernel_launch(void* const* d_in, const int* in_sizes, int n_in,
                              void* d_out, int out_size)
{
    const float* x   = (const float*)d_in[0];
    const float* adj = (const float*)d_in[1];
    const float* W   = (const float*)d_in[2];
    const float* a   = (const float*)d_in[3];
    float* out = (float*)d_out;

    cudaFuncSetAttribute(gat_prep, cudaFuncAttributeMaxDynamicSharedMemorySize,
                         PREP_SMEM);
    cudaFuncSetAttribute(gat_attn, cudaFuncAttributeMaxDynamicSharedMemorySize,
                         SMEMB_BYTES);

    gat_prep<<<N / 32, 64, PREP_SMEM>>>(x, W, a);
    gat_attn<<<dim3(N / TI, JSPLIT), TI, SMEMB_BYTES>>>(adj);
    gat_final<<<(N * FOUT) / 1024, 256>>>(out);
}